// round 2
// baseline (speedup 1.0000x reference)
#include <cuda_runtime.h>
#include <cuda_bf16.h>
#include <cstdint>
#include <cstddef>

#define N_CLASS 8192
#define FEAT    1024
#define BATCH   1024

#define TM 128
#define TN 128
#define TK 64
#define KTILES (FEAT / TK)        // 16
#define STAGES 3
#define A_BYTES (TM * 128)        // 16 KB (128 rows x 128B)
#define B_BYTES (TN * 128)        // 16 KB
#define STAGE_BYTES (A_BYTES + B_BYTES)
#define SMEM_TOTAL (STAGES * STAGE_BYTES)   // 96 KB

// ---------------- device scratch (no allocations allowed) ----------------
__device__ __nv_bfloat16 g_protos[(size_t)N_CLASS * FEAT];  // 16 MB bf16 protos after EMA
__device__ float         g_rowsum[N_CLASS];                 // sum_neg accumulators

// ---------------- helpers ----------------
__device__ __forceinline__ uint32_t smem_u32(const void* p) {
    uint32_t a;
    asm("{ .reg .u64 t; cvta.to.shared.u64 t, %1; cvt.u32.u64 %0, t; }" : "=r"(a) : "l"(p));
    return a;
}

__device__ __forceinline__ void ldmatrix_x4(uint32_t& r0, uint32_t& r1,
                                            uint32_t& r2, uint32_t& r3, uint32_t addr) {
    asm volatile("ldmatrix.sync.aligned.m8n8.x4.shared.b16 {%0,%1,%2,%3}, [%4];"
                 : "=r"(r0), "=r"(r1), "=r"(r2), "=r"(r3) : "r"(addr));
}

__device__ __forceinline__ void mma_bf16(float& c0, float& c1, float& c2, float& c3,
                                         uint32_t a0, uint32_t a1, uint32_t a2, uint32_t a3,
                                         uint32_t b0, uint32_t b1) {
    asm volatile(
        "mma.sync.aligned.m16n8k16.row.col.f32.bf16.bf16.f32 "
        "{%0,%1,%2,%3}, {%4,%5,%6,%7}, {%8,%9}, {%0,%1,%2,%3};"
        : "+f"(c0), "+f"(c1), "+f"(c2), "+f"(c3)
        : "r"(a0), "r"(a1), "r"(a2), "r"(a3), "r"(b0), "r"(b1));
}

// ============================================================================
// Kernel 1: per-class sequential EMA chain + fp32 -> bf16 convert + zero rowsum
// One block per class; 256 threads hold 4 floats each of the 1024-dim row.
// ============================================================================
__global__ void __launch_bounds__(256) ema_convert_kernel(
    const float* __restrict__ protos,
    const float* __restrict__ feats,
    const int*   __restrict__ labels)
{
    const int c = blockIdx.x;
    const int t = threadIdx.x;

    __shared__ int   s_cnt;
    __shared__ int   s_idx[256];
    __shared__ float s_red[8];

    if (t == 0) s_cnt = 0;
    __syncthreads();

    #pragma unroll
    for (int i = t; i < BATCH; i += 256) {
        if (labels[i] == c) {
            int p = atomicAdd(&s_cnt, 1);
            if (p < 256) s_idx[p] = i;
        }
    }
    __syncthreads();

    float4 r = reinterpret_cast<const float4*>(protos)[(size_t)c * (FEAT / 4) + t];

    const int cnt = min(s_cnt, 256);
    if (cnt > 0) {
        if (t == 0) {  // order matters: insertion-sort the (tiny) match list
            for (int a = 1; a < cnt; a++) {
                int v = s_idx[a], b = a - 1;
                while (b >= 0 && s_idx[b] > v) { s_idx[b + 1] = s_idx[b]; b--; }
                s_idx[b + 1] = v;
            }
        }
        __syncthreads();
        for (int m = 0; m < cnt; m++) {
            const int i = s_idx[m];
            float4 f = reinterpret_cast<const float4*>(feats)[(size_t)i * (FEAT / 4) + t];
            r.x = r.x * 0.95f + 0.05f * f.x;
            r.y = r.y * 0.95f + 0.05f * f.y;
            r.z = r.z * 0.95f + 0.05f * f.z;
            r.w = r.w * 0.95f + 0.05f * f.w;
            float ss = r.x * r.x + r.y * r.y + r.z * r.z + r.w * r.w;
            #pragma unroll
            for (int o = 16; o > 0; o >>= 1) ss += __shfl_xor_sync(0xffffffffu, ss, o);
            if ((t & 31) == 0) s_red[t >> 5] = ss;
            __syncthreads();
            float tot = s_red[0] + s_red[1] + s_red[2] + s_red[3]
                      + s_red[4] + s_red[5] + s_red[6] + s_red[7];
            float inv = 1.0f / fmaxf(sqrtf(tot), 1e-12f);
            r.x *= inv; r.y *= inv; r.z *= inv; r.w *= inv;
            __syncthreads();
        }
    }

    __nv_bfloat162 lo = __floats2bfloat162_rn(r.x, r.y);
    __nv_bfloat162 hi = __floats2bfloat162_rn(r.z, r.w);
    __nv_bfloat162* dst =
        reinterpret_cast<__nv_bfloat162*>(g_protos + (size_t)c * FEAT + (size_t)t * 4);
    dst[0] = lo;
    dst[1] = hi;

    if (t == 0) g_rowsum[c] = 0.0f;
}

// ============================================================================
// Kernel 2: fused symmetric Gram GEMM (bf16 mma.sync) + exp + row/col sums
// Upper-triangular 128x128 tiles; 3-stage cp.async pipeline; XOR-swizzled smem.
// Warps: 2 rows x 4 cols; warp tile 64x32; m16n8k16 fragments.
// ============================================================================
__global__ void __launch_bounds__(256, 2) gemm_exp_kernel()
{
    const int ti = blockIdx.y;
    const int tj = blockIdx.x;
    if (tj < ti) return;                 // symmetry: upper triangle only
    const bool diag   = (ti == tj);
    const int rowBase = ti * TM;
    const int colBase = tj * TN;

    extern __shared__ __align__(1024) char smem[];
    const uint32_t sb = smem_u32(smem);

    const int t   = threadIdx.x;
    const int wid = t >> 5;
    const int lid = t & 31;
    const int wr  = wid >> 2;            // 0..1  (64-row half)
    const int wc  = wid & 3;             // 0..3  (32-col quarter)

    const __nv_bfloat16* __restrict__ P = g_protos;

    // --- cp.async stage loader: 2048 16B chunks (A then B), 8 per thread ---
    auto load_stage = [&](int slot, int kt) {
        const uint32_t base = sb + slot * STAGE_BYTES;
        #pragma unroll
        for (int q = 0; q < 8; q++) {
            const int id  = t + q * 256;
            const int isB = id >> 10;
            const int l2  = id & 1023;
            const int row = l2 >> 3;      // 0..127
            const int kc  = l2 & 7;       // 16B chunk within 128B row
            const __nv_bfloat16* src =
                P + (size_t)((isB ? colBase : rowBase) + row) * FEAT + kt * TK + kc * 8;
            const uint32_t dst = base + isB * A_BYTES + row * 128 + ((kc ^ (row & 7)) << 4);
            asm volatile("cp.async.cg.shared.global [%0], [%1], 16;" :: "r"(dst), "l"(src));
        }
        asm volatile("cp.async.commit_group;" ::: "memory");
    };

    #pragma unroll
    for (int p = 0; p < STAGES; p++) load_stage(p, p);

    float acc[4][4][4];
    #pragma unroll
    for (int mf = 0; mf < 4; mf++)
        #pragma unroll
        for (int nf = 0; nf < 4; nf++)
            #pragma unroll
            for (int e = 0; e < 4; e++) acc[mf][nf][e] = 0.0f;

    const int lmod16 = lid & 15;
    const int ldiv16 = lid >> 4;

    for (int kt = 0; kt < KTILES; kt++) {
        asm volatile("cp.async.wait_group %0;" :: "n"(STAGES - 1) : "memory");
        __syncthreads();

        const uint32_t Abase = sb + (kt % STAGES) * STAGE_BYTES;
        const uint32_t Bbase = Abase + A_BYTES;

        #pragma unroll
        for (int ks = 0; ks < TK / 16; ks++) {      // 4 k16 steps
            const int kb = ks * 2 + ldiv16;         // 16B chunk index for this lane

            uint32_t a[4][4];
            #pragma unroll
            for (int mf = 0; mf < 4; mf++) {
                const int row = wr * 64 + mf * 16 + lmod16;
                ldmatrix_x4(a[mf][0], a[mf][1], a[mf][2], a[mf][3],
                            Abase + row * 128 + ((kb ^ (row & 7)) << 4));
            }
            uint32_t b[4][2];
            #pragma unroll
            for (int np = 0; np < 2; np++) {        // two n16 groups
                const int row = wc * 32 + np * 16 + lmod16;
                uint32_t r0, r1, r2, r3;
                ldmatrix_x4(r0, r1, r2, r3,
                            Bbase + row * 128 + ((kb ^ (row & 7)) << 4));
                b[np * 2 + 0][0] = r0; b[np * 2 + 0][1] = r2;   // n 0-7 of group
                b[np * 2 + 1][0] = r1; b[np * 2 + 1][1] = r3;   // n 8-15 of group
            }
            #pragma unroll
            for (int mf = 0; mf < 4; mf++)
                #pragma unroll
                for (int nf = 0; nf < 4; nf++)
                    mma_bf16(acc[mf][nf][0], acc[mf][nf][1],
                             acc[mf][nf][2], acc[mf][nf][3],
                             a[mf][0], a[mf][1], a[mf][2], a[mf][3],
                             b[nf][0], b[nf][1]);
        }
        __syncthreads();   // all warps done reading this slot
        if (kt + STAGES < KTILES) load_stage(kt % STAGES, kt + STAGES);
        else asm volatile("cp.async.commit_group;" ::: "memory");
    }

    // ---- epilogue: exp(10*x), row sums + (off-diag) butterfly column sums ----
    float* srow = reinterpret_cast<float*>(smem);        // [128]
    float* scol = srow + 128;                            // [128]
    __syncthreads();
    if (t < 256) srow[t] = 0.0f;                         // zeros both arrays
    __syncthreads();

    const int g  = lid >> 2;   // fragment row 0..7
    const int tg = lid & 3;    // fragment col group

    float cs[4][2];
    #pragma unroll
    for (int nf = 0; nf < 4; nf++) { cs[nf][0] = 0.0f; cs[nf][1] = 0.0f; }

    #pragma unroll
    for (int mf = 0; mf < 4; mf++) {
        float rs0 = 0.0f, rs1 = 0.0f;
        const int gr0 = rowBase + wr * 64 + mf * 16 + g;
        const int gr1 = gr0 + 8;
        #pragma unroll
        for (int nf = 0; nf < 4; nf++) {
            float e0 = __expf(acc[mf][nf][0] * 10.0f);
            float e1 = __expf(acc[mf][nf][1] * 10.0f);
            float e2 = __expf(acc[mf][nf][2] * 10.0f);
            float e3 = __expf(acc[mf][nf][3] * 10.0f);
            if (diag) {
                const int gc0 = colBase + wc * 32 + nf * 8 + 2 * tg;
                const int gc1 = gc0 + 1;
                if (gr0 == gc0) e0 = 0.0f;
                if (gr0 == gc1) e1 = 0.0f;
                if (gr1 == gc0) e2 = 0.0f;
                if (gr1 == gc1) e3 = 0.0f;
            }
            rs0 += e0 + e1;
            rs1 += e2 + e3;
            cs[nf][0] += e0 + e2;
            cs[nf][1] += e1 + e3;
        }
        rs0 += __shfl_xor_sync(0xffffffffu, rs0, 1);
        rs0 += __shfl_xor_sync(0xffffffffu, rs0, 2);
        rs1 += __shfl_xor_sync(0xffffffffu, rs1, 1);
        rs1 += __shfl_xor_sync(0xffffffffu, rs1, 2);
        if (tg == 0) {
            atomicAdd(&srow[wr * 64 + mf * 16 + g],     rs0);
            atomicAdd(&srow[wr * 64 + mf * 16 + g + 8], rs1);
        }
    }
    if (!diag) {
        #pragma unroll
        for (int nf = 0; nf < 4; nf++) {
            #pragma unroll
            for (int h = 0; h < 2; h++) {
                float v = cs[nf][h];
                v += __shfl_xor_sync(0xffffffffu, v, 4);
                v += __shfl_xor_sync(0xffffffffu, v, 8);
                v += __shfl_xor_sync(0xffffffffu, v, 16);
                if (g == 0)
                    atomicAdd(&scol[wc * 32 + nf * 8 + 2 * tg + h], v);
            }
        }
    }
    __syncthreads();
    if (t < 128) {
        atomicAdd(&g_rowsum[rowBase + t], srow[t]);
    } else if (!diag) {
        atomicAdd(&g_rowsum[colBase + t - 128], scol[t - 128]);
    }
}

// ============================================================================
// Kernel 3: loss = mean(log(rowsum / (C-1)))
// ============================================================================
__global__ void __launch_bounds__(256) finalize_kernel(float* __restrict__ out)
{
    const int t = threadIdx.x;
    float acc = 0.0f;
    for (int i = t; i < N_CLASS; i += 256)
        acc += logf(g_rowsum[i] * (1.0f / (float)(N_CLASS - 1)));
    #pragma unroll
    for (int o = 16; o > 0; o >>= 1) acc += __shfl_xor_sync(0xffffffffu, acc, o);
    __shared__ float s[8];
    if ((t & 31) == 0) s[t >> 5] = acc;
    __syncthreads();
    if (t == 0) {
        float v = s[0] + s[1] + s[2] + s[3] + s[4] + s[5] + s[6] + s[7];
        out[0] = v / (float)N_CLASS;
    }
}

// ============================================================================
extern "C" void kernel_launch(void* const* d_in, const int* in_sizes, int n_in,
                              void* d_out, int out_size)
{
    const float* features   = nullptr;
    const int*   labels     = nullptr;
    const float* prototypes = nullptr;
    for (int k = 0; k < n_in; k++) {
        if      (in_sizes[k] == BATCH)          labels     = (const int*)d_in[k];
        else if (in_sizes[k] == BATCH * FEAT)   features   = (const float*)d_in[k];
        else if (in_sizes[k] == N_CLASS * FEAT) prototypes = (const float*)d_in[k];
    }
    float* out = (float*)d_out;

    static bool attr_done = false;
    if (!attr_done) {
        cudaFuncSetAttribute(gemm_exp_kernel,
                             cudaFuncAttributeMaxDynamicSharedMemorySize, SMEM_TOTAL);
        attr_done = true;
    }

    ema_convert_kernel<<<N_CLASS, 256>>>(prototypes, features, labels);
    dim3 grid(N_CLASS / TN, N_CLASS / TM);
    gemm_exp_kernel<<<grid, 256, SMEM_TOTAL>>>();
    finalize_kernel<<<1, 256>>>(out);
    (void)out_size;
}